// round 17
// baseline (speedup 1.0000x reference)
#include <cuda_runtime.h>
#include <cstdint>

#define B_ 8
#define N_ 40000
#define C_ 80
#define TOPK_ 500
#define M_ (B_ * TOPK_)   // 4000
#define NANCH (B_ * N_)   // 320000
#define NBINS 4096
#define CANDCAP 2048
#define BLKS_PER_BATCH 625  // k1: 5000 blocks / 8 batches

// Fixed collect threshold: count(score >= T0) ~ 744 +/- 27 per batch for
// sigmoid(max of 80 N(0,1)) scores; exact histogram fallback covers any
// distribution where nsel falls outside [500, 1024].
#define T0_SCORE 0.9707f

// ---------------- scratch (device globals; no allocations) ----------------
__device__ float g_scores[NANCH];
__device__ int   g_labels[NANCH];
__device__ unsigned long long g_cand[B_ * CANDCAP];  // producer-side candidates
__device__ int      g_ccount[B_];        // zero at load; reset by NMS each run
__device__ int      g_bdone[B_];         // k1 blocks finished per batch
__device__ unsigned g_maxbits;           // monotone-uint max of gathered coords
__device__ unsigned g_nmsdone;           // NMS blocks finished (resetter elect)

__device__ __forceinline__ int score_bin(unsigned k) {
    int bin = ((int)(k >> 11)) - (0x3F000000 >> 11);
    return max(0, min(NBINS - 1, bin));
}

// ---------------- XLA-exact sigmoid: 0.5 + 0.5*fast_tanh(0.5x) ------------
__device__ __forceinline__ float jax_sigmoid(float x) {
    float t  = __fmul_rn(0.5f, x);                 // exact
    float at = fabsf(t);
    float tc = fminf(fmaxf(t, -7.99881172180175781f), 7.99881172180175781f);
    float x2 = __fmul_rn(tc, tc);
    float p = -2.76076847742355e-16f;
    p = fmaf(x2, p,  2.00018790482477e-13f);
    p = fmaf(x2, p, -8.60467152213735e-11f);
    p = fmaf(x2, p,  5.12229709037114e-08f);
    p = fmaf(x2, p,  1.48572235717979e-05f);
    p = fmaf(x2, p,  6.37261928875436e-04f);
    p = fmaf(x2, p,  4.89352455891786e-03f);
    p = __fmul_rn(tc, p);
    float q = 1.19825839466702e-06f;
    q = fmaf(x2, q, 1.18534705686654e-04f);
    q = fmaf(x2, q, 2.26843463243900e-03f);
    q = fmaf(x2, q, 4.89352518554385e-03f);
    float r  = __fdiv_rn(p, q);
    float th = (at < 0.0004f) ? t : r;
    return __fadd_rn(0.5f, __fmul_rn(0.5f, th));   // 0.5*th exact -> unambiguous
}

__device__ __forceinline__ unsigned mono_bits(float f) {
    int iv = __float_as_int(f);
    return (iv >= 0) ? ((unsigned)iv | 0x80000000u) : (unsigned)(~iv);
}

// ---------------- K1: scores + candidate append + inline per-batch top-k ---
// Main path (R15-proven): 4 lanes/anchor, streaming top-2 + shfl merge,
// exact sigmoid rescan fallback; candidates (score >= T0) appended to the
// per-batch global list. NEW: the LAST block of each batch (g_bdone count)
// runs the top-500 selection inline (threadFenceReduction pattern) -- the
// separate k2 kernel and its launch boundary are gone.
__global__ void __launch_bounds__(256, 6) k1_scores(const float* __restrict__ pconf,
                                                    const float* __restrict__ pboxes,
                                                    float* __restrict__ out) {
    __shared__ unsigned hist[NBINS];                 // 16KB (tail only)
    __shared__ unsigned long long sorted[1024];      // 8KB  (tail only)
    __shared__ unsigned wsum[8];
    __shared__ int s_islast, s_cnt;
    __shared__ unsigned s_maxb;

    const int gt  = blockIdx.x * 256 + threadIdx.x;
    const int a   = gt >> 2;
    const int sub = gt & 3;
    const int tid = threadIdx.x;
    const int lane = tid & 31;
    const unsigned gm = 0xFu << (lane & ~3);       // 4-lane group mask
    const int bidx = blockIdx.x / BLKS_PER_BATCH;  // batch of this block

    const float4* p = reinterpret_cast<const float4*>(pconf + (size_t)a * C_) + sub * 5;
    float4 v[5];
#pragma unroll
    for (int j = 0; j < 5; j++) v[j] = p[j];

    const int base = sub * 20;
    float m1 = -1e30f, m2 = -1e30f;
    int idx1 = 0;
#pragma unroll
    for (int j = 0; j < 5; j++) {
        float vals[4] = {v[j].x, v[j].y, v[j].z, v[j].w};
#pragma unroll
        for (int q = 0; q < 4; q++) {
            float val = vals[q];
            if (val > m1) { m2 = m1; m1 = val; idx1 = base + j * 4 + q; }
            else          { m2 = fmaxf(m2, val); }
        }
    }
#pragma unroll
    for (int d = 1; d < 4; d <<= 1) {
        float om1 = __shfl_xor_sync(gm, m1, d);
        float om2 = __shfl_xor_sync(gm, m2, d);
        int   oi  = __shfl_xor_sync(gm, idx1, d);
        if (om1 > m1 || (om1 == m1 && oi < idx1)) {
            m2 = fmaxf(m1, om2); m1 = om1; idx1 = oi;
        } else {
            m2 = fmaxf(om1, m2);
        }
    }

    float bs; int bl;
    if (m1 - m2 >= 1e-3f) {
        bs = jax_sigmoid(m1);
        bl = idx1;
    } else {
        // exact path (group-uniform branch): reload row (L1-hot) and rescan
        float thr = m1 - 1e-3f;
        bs = -1.0f; bl = 0x7FFFFFFF;
#pragma unroll
        for (int j = 0; j < 5; j++) {
            float4 w = p[j];
            float vals[4] = {w.x, w.y, w.z, w.w};
#pragma unroll
            for (int q = 0; q < 4; q++) {
                if (vals[q] > thr) {
                    float s = jax_sigmoid(vals[q]);
                    if (s > bs) { bs = s; bl = base + j * 4 + q; }
                }
            }
        }
#pragma unroll
        for (int d = 1; d < 4; d <<= 1) {
            float obs = __shfl_xor_sync(gm, bs, d);
            int   obl = __shfl_xor_sync(gm, bl, d);
            if (obs > bs || (obs == bs && obl < bl)) { bs = obs; bl = obl; }
        }
    }
    if (sub == 0) {
        g_scores[a] = bs;
        g_labels[a] = bl;
        if (bs >= T0_SCORE) {
            const unsigned li = (unsigned)(a - bidx * N_);
            int pos = atomicAdd(&g_ccount[bidx], 1);
            if (pos < CANDCAP) {
                unsigned k = __float_as_uint(bs);
                g_cand[bidx * CANDCAP + pos] =
                    ((unsigned long long)(~k) << 32) | li;
            }
        }
    }

    // ---------- last-block-of-batch election (threadFenceReduction) ----------
    if (tid == 0) {
        __threadfence();
        int done = atomicAdd(&g_bdone[bidx], 1);
        s_islast = (done == BLKS_PER_BATCH - 1) ? 1 : 0;
        s_maxb = 0u;
        s_cnt = 0;
    }
    __syncthreads();
    if (!s_islast) return;
    __threadfence();   // acquire: other blocks' g_cand/g_labels now visible

    // ===================== inline top-k tail (256 threads) =====================
    const int b = bidx;
    const unsigned BASE = __float_as_uint(T0_SCORE);
    const int wid = tid >> 5;

#pragma unroll
    for (int i = 0; i < 16; i++) hist[tid * 16 + i] = 0u;
    __syncthreads();

    const int nsel = g_ccount[b];
    const bool fast = (nsel >= TOPK_ && nsel <= 1024);
    const unsigned long long* res;

    if (fast) {
        // load <=4 cands/thread, bucket-histogram on score high bits
        unsigned long long myv[4];
        unsigned myrb[4];
        int mycnt = 0;
#pragma unroll
        for (int j = 0; j < 4; j++) {
            int i2 = tid + j * 256;
            if (i2 < nsel) {
                unsigned long long vv = g_cand[b * CANDCAP + i2];
                unsigned k = ~((unsigned)(vv >> 32));
                unsigned rb = 4095u - min(4095u, (k - BASE) >> 7);
                myv[mycnt] = vv; myrb[mycnt] = rb; mycnt++;
                atomicAdd(&hist[rb], 1u);
            }
        }
        __syncthreads();

        // exclusive scan of 4096 bins: 16 bins/thread + warp scan + 8-warp fix
        unsigned h[16]; unsigned ssum = 0;
#pragma unroll
        for (int i = 0; i < 16; i++) { h[i] = hist[tid * 16 + i]; ssum += h[i]; }
        unsigned inc = ssum;
#pragma unroll
        for (int d = 1; d < 32; d <<= 1) {
            unsigned n = __shfl_up_sync(0xFFFFFFFFu, inc, d);
            if (lane >= d) inc += n;
        }
        if (lane == 31) wsum[wid] = inc;
        __syncthreads();
        if (tid == 0) {
            unsigned acc = 0;
#pragma unroll
            for (int i = 0; i < 8; i++) { unsigned t = wsum[i]; wsum[i] = acc; acc += t; }
        }
        __syncthreads();
        unsigned run = wsum[wid] + (inc - ssum);
#pragma unroll
        for (int i = 0; i < 16; i++) { hist[tid * 16 + i] = run; run += h[i]; }
        __syncthreads();

        // scatter (hist: start -> end in place)
        for (int j = 0; j < mycnt; j++) {
            unsigned pos = atomicAdd(&hist[myrb[j]], 1u);
            sorted[pos] = myv[j];
        }
        __syncthreads();

        // per-bucket stable insertion sort (full (~key,idx) compare erases
        // all append/scatter nondeterminism -> exact jax top_k order)
        for (int r = tid; r < NBINS; r += 256) {
            int st = r ? (int)hist[r - 1] : 0;
            int en = (int)hist[r];
            for (int i2 = st + 1; i2 < en; i2++) {
                unsigned long long vv = sorted[i2];
                int jx = i2;
                while (jx > st && sorted[jx - 1] > vv) {
                    sorted[jx] = sorted[jx - 1]; jx--;
                }
                sorted[jx] = vv;
            }
        }
        __syncthreads();
        res = sorted;
    } else {
        // ---- exact fallback (cold): histogram pivot over g_scores, collect
        // into g_cand, global bitonic sort ----
        const float* sc = g_scores + b * N_;
        for (int i = tid; i < N_; i += 256)
            atomicAdd(&hist[score_bin(__float_as_uint(sc[i]))], 1u);
        __syncthreads();
        if (tid == 0) {
            unsigned cum = 0; int P = 0;
            for (int bin = NBINS - 1; bin >= 0; bin--) {
                cum += hist[bin];
                if (cum >= TOPK_) { P = bin; break; }
            }
            s_cnt = 0;
            wsum[0] = (unsigned)P;
        }
        __syncthreads();
        const int P = (int)wsum[0];
        for (int i = tid; i < N_; i += 256) {
            unsigned k = __float_as_uint(sc[i]);
            if (score_bin(k) >= P) {
                int pos = atomicAdd(&s_cnt, 1);
                if (pos < CANDCAP)
                    g_cand[b * CANDCAP + pos] =
                        ((unsigned long long)(~k) << 32) | (unsigned)i;
            }
        }
        __syncthreads();
        for (int i = tid; i < CANDCAP; i += 256)
            if (i >= s_cnt) g_cand[b * CANDCAP + i] = ~0ULL;
        __syncthreads();
        unsigned long long* gc = &g_cand[b * CANDCAP];
        for (int kk = 2; kk <= CANDCAP; kk <<= 1) {
            for (int j = kk >> 1; j > 0; j >>= 1) {
                for (int i = tid; i < CANDCAP; i += 256) {
                    int l = i ^ j;
                    if (l > i) {
                        unsigned long long x = gc[i], y = gc[l];
                        bool up = ((i & kk) == 0);
                        if ((x > y) == up) { gc[i] = y; gc[l] = x; }
                    }
                }
                __syncthreads();
            }
        }
        res = gc;
    }

    // emit top-500 (2 per thread) + maxbits over gathered boxes
#pragma unroll
    for (int j = 0; j < 2; j++) {
        int t2 = tid + j * 256;
        if (t2 < TOPK_) {
            unsigned long long skv = res[t2];
            unsigned idx = (unsigned)(skv & 0xFFFFFFFFu);
            unsigned kb  = ~((unsigned)(skv >> 32));
            float score  = __uint_as_float(kb);
            int m = b * TOPK_ + t2;
            out[m] = (float)b;                                      // ids_batch1
            float4 box = reinterpret_cast<const float4*>(pboxes)[b * N_ + idx];
            reinterpret_cast<float4*>(out + M_)[m] = box;           // p_boxes1
            out[5 * M_ + m] = (float)g_labels[b * N_ + idx];        // p_labels1
            out[6 * M_ + m] = score;                                // p_scores1
            unsigned lm = max(max(mono_bits(box.x), mono_bits(box.y)),
                              max(mono_bits(box.z), mono_bits(box.w)));
            atomicMax(&s_maxb, lm);
        }
    }
    __syncthreads();
    if (tid == 0) atomicMax(&g_maxbits, s_maxb);
}

// ---------------- K3: warp-per-group greedy NMS (exact offset arith) -------
// 640 groups = (label, batch); cross-group IoU is exactly 0 (offset spacing
// >= 2.1 exceeds box extents), so per-group greedy in rank order == jax's
// global greedy. Last-finisher block resets all counters for graph replay.
__global__ void __launch_bounds__(128) k3_nms(float* __restrict__ out) {
    __shared__ float4 kept_s[4][512];
    const int lane = threadIdx.x & 31;
    const int wid  = threadIdx.x >> 5;
    const int g    = blockIdx.x * 4 + wid;      // 0..639
    const int bb   = g & 7;
    const float fc = (float)(g >> 3);
    const unsigned gm = 0xFFFFFFFFu;

    unsigned mb = g_maxbits;
    int ivb = (mb & 0x80000000u) ? (int)(mb & 0x7FFFFFFFu) : ~((int)mb);
    const float mc1 = __fadd_rn(__int_as_float(ivb), 1.0f);
    const float off = __fmul_rn((float)g, mc1);

    float4* kept = kept_s[wid];
    int nk = 0;

    for (int it = 0; it < 16; it++) {
        int r = it * 32 + lane;
        int m = bb * TOPK_ + r;
        bool pred = false;
        if (r < TOPK_) {
            float lab = out[5 * M_ + m];
            float scv = out[6 * M_ + m];
            bool valid = scv > 0.05f;
            pred = valid && (lab == fc);
            if (!valid && fc == 0.0f) out[7 * M_ + m] = 0.0f;  // invalid: keep=0
        }
        unsigned ball = __ballot_sync(gm, pred);
        float4 ob;
        if (pred) {
            float4 bx = reinterpret_cast<float4*>(out + M_)[m];
            ob.x = __fadd_rn(bx.x, off); ob.y = __fadd_rn(bx.y, off);
            ob.z = __fadd_rn(bx.z, off); ob.w = __fadd_rn(bx.w, off);
        }
        while (ball) {
            int src = __ffs(ball) - 1; ball &= ball - 1;
            float4 cb;
            cb.x = __shfl_sync(gm, ob.x, src);
            cb.y = __shfl_sync(gm, ob.y, src);
            cb.z = __shfl_sync(gm, ob.z, src);
            cb.w = __shfl_sync(gm, ob.w, src);
            bool sup = false;
            for (int t = lane; t < nk; t += 32) {
                float4 kb = kept[t];
                float ltx = fmaxf(kb.x, cb.x), lty = fmaxf(kb.y, cb.y);
                float rbx = fminf(kb.z, cb.z), rby = fminf(kb.w, cb.w);
                float wx = fmaxf(__fsub_rn(rbx, ltx), 0.0f);
                float wy = fmaxf(__fsub_rn(rby, lty), 0.0f);
                float inter = __fmul_rn(wx, wy);
                float aa = __fmul_rn(__fsub_rn(kb.z, kb.x), __fsub_rn(kb.w, kb.y));
                float ab = __fmul_rn(__fsub_rn(cb.z, cb.x), __fsub_rn(cb.w, cb.y));
                float un = __fsub_rn(__fadd_rn(aa, ab), inter);
                float iou = __fdiv_rn(inter, fmaxf(un, 1e-9f));
                if (iou > 0.5f) sup = true;
            }
            unsigned sb = __ballot_sync(gm, sup);
            bool keepit = (sb == 0u);
            if (lane == src)
                out[7 * M_ + bb * TOPK_ + it * 32 + src] = keepit ? 1.0f : 0.0f;
            if (keepit) {
                if (lane == 0) kept[nk] = cb;
                nk++;
                __syncwarp(gm);
            }
        }
    }

    // last NMS block to FINISH resets all inter-launch state (all other
    // blocks have already read g_maxbits by the time they incremented)
    __syncthreads();
    if (threadIdx.x == 0) {
        __threadfence();
        unsigned r = atomicAdd(&g_nmsdone, 1u);
        if (r == 159u) {
            g_maxbits = 0u;
#pragma unroll
            for (int i = 0; i < B_; i++) { g_ccount[i] = 0; g_bdone[i] = 0; }
            __threadfence();
            atomicExch(&g_nmsdone, 0u);
        }
    }
}

// ---------------- host ----------------
extern "C" void kernel_launch(void* const* d_in, const int* in_sizes, int n_in,
                              void* d_out, int out_size) {
    const float* pconf  = (const float*)d_in[0];
    const float* pboxes = (const float*)d_in[1];
    float* out = (float*)d_out;
    (void)in_sizes; (void)n_in; (void)out_size;

    k1_scores<<<NANCH * 4 / 256, 256>>>(pconf, pboxes, out);
    k3_nms<<<160, 128>>>(out);
}